// round 14
// baseline (speedup 1.0000x reference)
#include <cuda_runtime.h>
#include <cuda_bf16.h>
#include <math.h>
#include <stdint.h>

#define B_  8
#define L_  8
#define C_  64
#define P_  1024
#define NH_ 128
#define MCH 512

// ---------------- scratch (static device memory) -----------------------------
__device__ float g_Opart[4][B_][P_][C_];
__device__ float g_m[4][B_][P_];
__device__ float g_l[4][B_][P_];
__device__ float g_xs[B_][C_][P_];
__device__ float g_xc[B_][C_][P_];
__device__ float g_att[B_][C_][MCH];
__device__ float g_attp[2][B_][C_][MCH];
__device__ float g_y1[2][B_][C_][P_];
__device__ float g_part[2][B_][8][2];
__device__ float g_stats[2][B_][2];
__device__ __align__(16) __nv_bfloat16 g_Kh[B_ * L_ * P_ * C_];
__device__ __align__(16) __nv_bfloat16 g_Ke[B_ * L_ * P_ * C_];
__device__ __align__(16) __nv_bfloat16 g_Vh[B_ * L_ * P_ * C_];
__device__ __align__(16) __nv_bfloat16 g_Ve[B_ * L_ * P_ * C_];
// conv1 weights, bf16 h/e, layout [st][tap][co][ci]
__device__ __align__(16) __nv_bfloat16 g_W1h[2 * 25 * 64 * 64];
__device__ __align__(16) __nv_bfloat16 g_W1e[2 * 25 * 64 * 64];

// ---------------- helpers -----------------------------------------------------
__device__ __forceinline__ uint32_t smem_u32(const void* p) {
    uint32_t a;
    asm("{ .reg .u64 t; cvta.to.shared.u64 t, %1; cvt.u32.u64 %0, t; }"
        : "=r"(a) : "l"(p));
    return a;
}
__device__ __forceinline__ void ldsm4(uint32_t* r, uint32_t addr) {
    asm volatile("ldmatrix.sync.aligned.m8n8.x4.shared.b16 {%0,%1,%2,%3}, [%4];"
        : "=r"(r[0]), "=r"(r[1]), "=r"(r[2]), "=r"(r[3]) : "r"(addr));
}
__device__ __forceinline__ void ldsm4t(uint32_t* r, uint32_t addr) {
    asm volatile("ldmatrix.sync.aligned.m8n8.x4.trans.shared.b16 {%0,%1,%2,%3}, [%4];"
        : "=r"(r[0]), "=r"(r[1]), "=r"(r[2]), "=r"(r[3]) : "r"(addr));
}
__device__ __forceinline__ void mma16816(float* d, const uint32_t* a,
                                         uint32_t b0, uint32_t b1) {
    asm volatile("mma.sync.aligned.m16n8k16.row.col.f32.bf16.bf16.f32 "
        "{%0,%1,%2,%3}, {%4,%5,%6,%7}, {%8,%9}, {%0,%1,%2,%3};"
        : "+f"(d[0]), "+f"(d[1]), "+f"(d[2]), "+f"(d[3])
        : "r"(a[0]), "r"(a[1]), "r"(a[2]), "r"(a[3]), "r"(b0), "r"(b1));
}
__device__ __forceinline__ uint32_t bf2pack(float lo, float hi) {
    uint32_t r;
    asm("cvt.rn.bf16x2.f32 %0, %1, %2;" : "=r"(r) : "f"(hi), "f"(lo));
    return r;
}
__device__ __forceinline__ void cp16(uint32_t saddr, const void* g) {
    asm volatile("cp.async.cg.shared.global [%0], [%1], 16;"
                 :: "r"(saddr), "l"(g) : "memory");
}
#define CP_COMMIT() asm volatile("cp.async.commit_group;" ::: "memory")
#define CP_WAIT0()  asm volatile("cp.async.wait_group 0;" ::: "memory")
__device__ __forceinline__ uint32_t swz(int row, int chunk) {
    return (uint32_t)(row * 128 + ((chunk ^ (row & 7)) << 4));
}

// =============================================================================
// 0a) Conv1 weight pre-pass: fp32 [co][ci][5][5] -> bf16 h/e [st][tap][co][ci].
//     grid (25, 2), 256 threads.
// =============================================================================
__global__ __launch_bounds__(256, 1)
void convert_w1_kernel(const float* __restrict__ s_w1,
                       const float* __restrict__ c_w1)
{
    const int tap = blockIdx.x;
    const int st  = blockIdx.y;
    const float* w = st ? c_w1 : s_w1;
    const int tid = threadIdx.x;
    for (int i = tid; i < 4096; i += 256) {
        int co = i >> 6, ci = i & 63;
        float v = w[co * 1600 + ci * 25 + tap];
        __nv_bfloat16 h = __float2bfloat16(v);
        size_t dst = ((size_t)(st * 25 + tap) * 64 + co) * 64 + ci;
        g_W1h[dst] = h;
        g_W1e[dst] = __float2bfloat16(v - __bfloat162float(h));
    }
}

// =============================================================================
// 0b) KV pre-pass: fp32 [b][l][c][p] -> bf16 h/e in [b][l][p][c]. grid (64, 2).
// =============================================================================
__global__ __launch_bounds__(256, 1)
void convert_kv_kernel(const float* __restrict__ keys,
                       const float* __restrict__ vals)
{
    __shared__ __nv_bfloat16 shH[64][68], shE[64][68];
    const int bl = blockIdx.x;
    const int kv = blockIdx.y;
    const int tid = threadIdx.x;
    const float* src = (kv ? vals : keys) + (size_t)bl * 65536;
    __nv_bfloat16* dh = (kv ? g_Vh : g_Kh) + (size_t)bl * 65536;
    __nv_bfloat16* de = (kv ? g_Ve : g_Ke) + (size_t)bl * 65536;

    for (int it = 0; it < 16; ++it) {
        const int p0 = it * 64;
        __syncthreads();
        for (int i4 = tid; i4 < 1024; i4 += 256) {
            int c = i4 >> 4, p4 = (i4 & 15) << 2;
            float4 v = *(const float4*)(src + c * P_ + p0 + p4);
            float vv[4] = {v.x, v.y, v.z, v.w};
#pragma unroll
            for (int u = 0; u < 4; u++) {
                __nv_bfloat16 h = __float2bfloat16(vv[u]);
                shH[p4 + u][c] = h;
                shE[p4 + u][c] = __float2bfloat16(vv[u] - __bfloat162float(h));
            }
        }
        __syncthreads();
        for (int i4 = tid; i4 < 1024; i4 += 256) {
            int p = i4 >> 4, c4 = (i4 & 15) << 2;
            size_t o = (size_t)(p0 + p) * 64 + c4;
            *(uint2*)(dh + o) = *(const uint2*)&shH[p][c4];
            *(uint2*)(de + o) = *(const uint2*)&shE[p][c4];
        }
    }
}

// =============================================================================
// 1) Flash spatial attention. 128 threads, TQ=64, ks=4. grid (4,16,8).
// =============================================================================
#define KVB 32768
#define FL_SMEM 65536

__global__ __launch_bounds__(128, 3)
void flash_mma_kernel(const float* __restrict__ q)
{
    extern __shared__ char smem[];
    const uint32_t sb = smem_u32(smem);
    const int ks = blockIdx.x;
    const int qt = blockIdx.y;
    const int b  = blockIdx.z;
    const int tid = threadIdx.x;
    const int wid = tid >> 5;
    const int lane = tid & 31;

    const int l7 = lane & 7;
    const int a_row = wid * 16 + l7 + ((lane >> 3) & 1) * 8;
    const int a_co  = lane >> 4;
    const int hi16  = lane >> 4;
    const int c8    = (lane >> 3) & 1;
    const int grp   = lane >> 2;
    const int qr_lo = wid * 16 + grp;
    const int qr_hi = qr_lo + 8;

    const int kbase = b * 8192 + ks * 2048;

    const float* qg = q + (size_t)b * C_ * P_ + qt * 64;
    for (int i = tid; i < 4096; i += 128) {
        int c = i >> 6, qq = i & 63;
        float v = qg[c * P_ + qq];
        __nv_bfloat16 h = __float2bfloat16(v);
        uint32_t byo = swz(qq, c >> 3) + (c & 7) * 2;
        *(__nv_bfloat16*)(smem + byo) = h;
        *(__nv_bfloat16*)(smem + 8192 + byo) =
            __float2bfloat16(v - __bfloat162float(h));
    }
    __syncthreads();

    uint32_t qhf[4][4], qef[4][4];
#pragma unroll
    for (int t4 = 0; t4 < 4; t4++) {
        ldsm4(qhf[t4], sb + swz(a_row, 2 * t4 + a_co));
        ldsm4(qef[t4], sb + 8192 + swz(a_row, 2 * t4 + a_co));
    }
    __syncthreads();

    {
        const size_t gb = (size_t)kbase * 64;
#pragma unroll
        for (int kk = 0; kk < 16; kk++) {
            int i = tid + 128 * kk;
            int buf = i >> 9;
            int j = i & 511;
            int r = j >> 3, cx = j & 7;
            const __nv_bfloat16* gp =
                (buf == 0) ? g_Kh : (buf == 1) ? g_Ke : (buf == 2) ? g_Vh : g_Ve;
            cp16(sb + buf * 8192 + swz(r, cx), gp + gb + (size_t)r * 64 + cx * 8);
        }
        CP_COMMIT();
    }

    float sd[8][4];
    float od[8][4];
    float m_lo = -1e30f, m_hi = -1e30f, l_lo = 0.f, l_hi = 0.f;
#pragma unroll
    for (int j = 0; j < 8; j++)
#pragma unroll
        for (int x = 0; x < 4; x++) od[j][x] = 0.f;

    for (int t = 0; t < 32; ++t) {
        CP_WAIT0();
        __syncthreads();
        const uint32_t bufb = sb + (t & 1) * KVB;

        if (t < 31) {
            const uint32_t ob = sb + ((t + 1) & 1) * KVB;
            const size_t gb = (size_t)(kbase + (t + 1) * 64) * 64;
#pragma unroll
            for (int kk = 0; kk < 16; kk++) {
                int i = tid + 128 * kk;
                int buf = i >> 9;
                int j = i & 511;
                int r = j >> 3, cx = j & 7;
                const __nv_bfloat16* gp =
                    (buf == 0) ? g_Kh : (buf == 1) ? g_Ke : (buf == 2) ? g_Vh : g_Ve;
                cp16(ob + buf * 8192 + swz(r, cx), gp + gb + (size_t)r * 64 + cx * 8);
            }
            CP_COMMIT();
        }

        const uint32_t SKH = bufb, SKE = bufb + 8192;
        const uint32_t SVH = bufb + 16384, SVE = bufb + 24576;

#pragma unroll
        for (int j = 0; j < 8; j++)
#pragma unroll
            for (int x = 0; x < 4; x++) sd[j][x] = 0.f;

#pragma unroll
        for (int t4 = 0; t4 < 4; t4++) {
#pragma unroll
            for (int jp = 0; jp < 4; jp++) {
                uint32_t kaddr_row = 8 * (2 * jp + hi16) + l7;
                uint32_t kh4[4], ke4[4];
                ldsm4(kh4, SKH + swz(kaddr_row, 2 * t4 + c8));
                ldsm4(ke4, SKE + swz(kaddr_row, 2 * t4 + c8));
                mma16816(sd[2 * jp],     qhf[t4], kh4[0], kh4[1]);
                mma16816(sd[2 * jp + 1], qhf[t4], kh4[2], kh4[3]);
                mma16816(sd[2 * jp],     qhf[t4], ke4[0], ke4[1]);
                mma16816(sd[2 * jp + 1], qhf[t4], ke4[2], ke4[3]);
                mma16816(sd[2 * jp],     qef[t4], kh4[0], kh4[1]);
                mma16816(sd[2 * jp + 1], qef[t4], kh4[2], kh4[3]);
            }
        }

        float mx_lo = sd[0][0], mx_hi = sd[0][2];
#pragma unroll
        for (int j = 0; j < 8; j++) {
            mx_lo = fmaxf(mx_lo, fmaxf(sd[j][0], sd[j][1]));
            mx_hi = fmaxf(mx_hi, fmaxf(sd[j][2], sd[j][3]));
        }
        mx_lo = fmaxf(mx_lo, __shfl_xor_sync(0xffffffffu, mx_lo, 1));
        mx_lo = fmaxf(mx_lo, __shfl_xor_sync(0xffffffffu, mx_lo, 2));
        mx_hi = fmaxf(mx_hi, __shfl_xor_sync(0xffffffffu, mx_hi, 1));
        mx_hi = fmaxf(mx_hi, __shfl_xor_sync(0xffffffffu, mx_hi, 2));
        float mn_lo = fmaxf(m_lo, mx_lo), mn_hi = fmaxf(m_hi, mx_hi);
        float al_lo = __expf(m_lo - mn_lo), al_hi = __expf(m_hi - mn_hi);
        m_lo = mn_lo; m_hi = mn_hi;

        float rs_lo = 0.f, rs_hi = 0.f;
#pragma unroll
        for (int j = 0; j < 8; j++) {
            sd[j][0] = __expf(sd[j][0] - mn_lo);
            sd[j][1] = __expf(sd[j][1] - mn_lo);
            sd[j][2] = __expf(sd[j][2] - mn_hi);
            sd[j][3] = __expf(sd[j][3] - mn_hi);
            rs_lo += sd[j][0] + sd[j][1];
            rs_hi += sd[j][2] + sd[j][3];
        }
        rs_lo += __shfl_xor_sync(0xffffffffu, rs_lo, 1);
        rs_lo += __shfl_xor_sync(0xffffffffu, rs_lo, 2);
        rs_hi += __shfl_xor_sync(0xffffffffu, rs_hi, 1);
        rs_hi += __shfl_xor_sync(0xffffffffu, rs_hi, 2);
        l_lo = l_lo * al_lo + rs_lo;
        l_hi = l_hi * al_hi + rs_hi;

#pragma unroll
        for (int j = 0; j < 8; j++) {
            od[j][0] *= al_lo; od[j][1] *= al_lo;
            od[j][2] *= al_hi; od[j][3] *= al_hi;
        }

        uint32_t pha[4][4], pea[4][4];
#pragma unroll
        for (int t4 = 0; t4 < 4; t4++) {
            int j0 = 2 * t4, j1 = 2 * t4 + 1;
            float e[8];
#pragma unroll
            for (int u = 0; u < 4; u++) {
                float p0f = sd[j0][u];
                float p1f = sd[j1][u];
                e[u]     = p0f - __bfloat162float(__float2bfloat16(p0f));
                e[4 + u] = p1f - __bfloat162float(__float2bfloat16(p1f));
            }
            pha[t4][0] = bf2pack(sd[j0][0], sd[j0][1]);
            pha[t4][1] = bf2pack(sd[j0][2], sd[j0][3]);
            pha[t4][2] = bf2pack(sd[j1][0], sd[j1][1]);
            pha[t4][3] = bf2pack(sd[j1][2], sd[j1][3]);
            pea[t4][0] = bf2pack(e[0], e[1]);
            pea[t4][1] = bf2pack(e[2], e[3]);
            pea[t4][2] = bf2pack(e[4], e[5]);
            pea[t4][3] = bf2pack(e[6], e[7]);
        }

#pragma unroll
        for (int t4 = 0; t4 < 4; t4++) {
            uint32_t vrow = 16 * t4 + l7 + 8 * c8;
#pragma unroll
            for (int jp = 0; jp < 4; jp++) {
                int j2 = 2 * jp;
                uint32_t vh4[4], ve4[4];
                ldsm4t(vh4, SVH + swz(vrow, j2 + hi16));
                ldsm4t(ve4, SVE + swz(vrow, j2 + hi16));
                mma16816(od[j2],     pha[t4], vh4[0], vh4[1]);
                mma16816(od[j2 + 1], pha[t4], vh4[2], vh4[3]);
                mma16816(od[j2],     pea[t4], vh4[0], vh4[1]);
                mma16816(od[j2 + 1], pea[t4], vh4[2], vh4[3]);
                mma16816(od[j2],     pha[t4], ve4[0], ve4[1]);
                mma16816(od[j2 + 1], pha[t4], ve4[2], ve4[3]);
            }
        }
    }

    if ((lane & 3) == 0) {
        g_m[ks][b][qt * 64 + qr_lo] = m_lo;
        g_l[ks][b][qt * 64 + qr_lo] = l_lo;
        g_m[ks][b][qt * 64 + qr_hi] = m_hi;
        g_l[ks][b][qt * 64 + qr_hi] = l_hi;
    }
#pragma unroll
    for (int j2 = 0; j2 < 8; j2++) {
        int c = 8 * j2 + (lane & 3) * 2;
        g_Opart[ks][b][qt * 64 + qr_lo][c]     = od[j2][0];
        g_Opart[ks][b][qt * 64 + qr_lo][c + 1] = od[j2][1];
        g_Opart[ks][b][qt * 64 + qr_hi][c]     = od[j2][2];
        g_Opart[ks][b][qt * 64 + qr_hi][c + 1] = od[j2][3];
    }
}

// =============================================================================
// 2) Merge 4 key-splits + residual. grid (8, 8), 256 threads.
// =============================================================================
__global__ void combine_kernel(const float* __restrict__ q)
{
    const int qt = blockIdx.x;
    const int b  = blockIdx.y;
    const int tid = threadIdx.x;
    for (int i = tid; i < 128 * 64; i += 256) {
        int qq = qt * 128 + (i >> 6);
        int c  = i & 63;
        float m0 = g_m[0][b][qq], m1 = g_m[1][b][qq];
        float m2 = g_m[2][b][qq], m3 = g_m[3][b][qq];
        float M  = fmaxf(fmaxf(m0, m1), fmaxf(m2, m3));
        float e0 = __expf(m0 - M), e1 = __expf(m1 - M);
        float e2 = __expf(m2 - M), e3 = __expf(m3 - M);
        float denom = g_l[0][b][qq] * e0 + g_l[1][b][qq] * e1 +
                      g_l[2][b][qq] * e2 + g_l[3][b][qq] * e3;
        float val = (g_Opart[0][b][qq][c] * e0 + g_Opart[1][b][qq][c] * e1 +
                     g_Opart[2][b][qq][c] * e2 + g_Opart[3][b][qq][c] * e3) / denom;
        g_xs[b][c][qq] = val + q[((size_t)b * C_ + c) * P_ + qq];
    }
}

// =============================================================================
// 3) Channel logit partials. grid (mt=8, nh=2, b=8), 256 threads.
// =============================================================================
#define CLS 132
#define CL_SMEM (2 * 64 * CLS * 4)

__global__ __launch_bounds__(256, 1)
void ca_logits_kernel(const float* __restrict__ q,
                      const float* __restrict__ keys)
{
    extern __shared__ float sm[];
    float* Qs = sm;
    float* Ks = sm + 64 * CLS;
    const int mt = blockIdx.x;
    const int nh = blockIdx.y;
    const int b  = blockIdx.z;
    const int tid = threadIdx.x;
    const int ty = tid >> 4, tx = tid & 15;

    float acc[4][4];
#pragma unroll
    for (int i = 0; i < 4; i++)
#pragma unroll
        for (int j = 0; j < 4; j++) acc[i][j] = 0.f;

    const float* qb = q + (size_t)b * C_ * P_ + nh * 512;
    const float* kb = keys + (size_t)b * MCH * P_ + nh * 512;

    for (int nt = 0; nt < 4; ++nt) {
        __syncthreads();
        for (int i4 = tid; i4 < 2048; i4 += 256) {
            int r = i4 >> 5, n4 = (i4 & 31) << 2;
            *(float4*)&Qs[r * CLS + n4] = *(const float4*)(qb + r * P_ + nt * 128 + n4);
            *(float4*)&Ks[r * CLS + n4] =
                *(const float4*)(kb + (size_t)(mt * 64 + r) * P_ + nt * 128 + n4);
        }
        __syncthreads();
#pragma unroll 4
        for (int n = 0; n < 128; ++n) {
            float qv[4], kv[4];
#pragma unroll
            for (int i = 0; i < 4; i++) qv[i] = Qs[(ty + 16 * i) * CLS + n];
#pragma unroll
            for (int j = 0; j < 4; j++) kv[j] = Ks[(tx + 16 * j) * CLS + n];
#pragma unroll
            for (int i = 0; i < 4; i++)
#pragma unroll
                for (int j = 0; j < 4; j++)
                    acc[i][j] = fmaf(qv[i], kv[j], acc[i][j]);
        }
    }
#pragma unroll
    for (int i = 0; i < 4; i++)
#pragma unroll
        for (int j = 0; j < 4; j++)
            g_attp[nh][b][ty + 16 * i][mt * 64 + tx + 16 * j] = acc[i][j];
}

// =============================================================================
// 4) Row softmax (sums partials). grid (64, 8), 128 threads.
// =============================================================================
__global__ void ca_softmax_kernel()
{
    const int c = blockIdx.x;
    const int b = blockIdx.y;
    const int tid = threadIdx.x;
    float v[4];
#pragma unroll
    for (int r = 0; r < 4; r++)
        v[r] = g_attp[0][b][c][tid + 128 * r] + g_attp[1][b][c][tid + 128 * r];
    float mx = fmaxf(fmaxf(v[0], v[1]), fmaxf(v[2], v[3]));
#pragma unroll
    for (int off = 16; off > 0; off >>= 1)
        mx = fmaxf(mx, __shfl_xor_sync(0xffffffffu, mx, off));
    __shared__ float red[4], red2[4];
    if ((tid & 31) == 0) red[tid >> 5] = mx;
    __syncthreads();
    mx = fmaxf(fmaxf(red[0], red[1]), fmaxf(red[2], red[3]));
    float s = 0.f;
#pragma unroll
    for (int r = 0; r < 4; r++) { v[r] = __expf(v[r] - mx); s += v[r]; }
#pragma unroll
    for (int off = 16; off > 0; off >>= 1)
        s += __shfl_xor_sync(0xffffffffu, s, off);
    if ((tid & 31) == 0) red2[tid >> 5] = s;
    __syncthreads();
    s = red2[0] + red2[1] + red2[2] + red2[3];
    float inv = 1.f / s;
#pragma unroll
    for (int r = 0; r < 4; r++) g_att[b][c][tid + 128 * r] = v[r] * inv;
}

// =============================================================================
// 5) Channel apply + residual. grid (nt=16, b=8), 128 threads.
// =============================================================================
__global__ __launch_bounds__(128, 1)
void ca_apply_kernel(const float* __restrict__ q,
                     const float* __restrict__ vals)
{
    __shared__ float As[128 * 68];
    const int nt = blockIdx.x;
    const int b  = blockIdx.y;
    const int tid = threadIdx.x;
    const int n  = nt * 64 + (tid & 63);
    const int cg = tid >> 6;

    float acc[32];
#pragma unroll
    for (int j = 0; j < 32; j++) acc[j] = 0.f;

    const float* vb = vals + (size_t)b * MCH * P_;

    for (int mc = 0; mc < 4; ++mc) {
        __syncthreads();
        for (int i = tid; i < 8192; i += 128) {
            int c = i >> 7, mm = i & 127;
            As[mm * 68 + c] = g_att[b][c][mc * 128 + mm];
        }
        __syncthreads();
#pragma unroll 2
        for (int mm = 0; mm < 128; ++mm) {
            float vv = vb[(size_t)(mc * 128 + mm) * P_ + n];
#pragma unroll
            for (int u = 0; u < 8; ++u) {
                float4 a4 = *(const float4*)&As[mm * 68 + cg * 32 + 4 * u];
                acc[4 * u + 0] = fmaf(a4.x, vv, acc[4 * u + 0]);
                acc[4 * u + 1] = fmaf(a4.y, vv, acc[4 * u + 1]);
                acc[4 * u + 2] = fmaf(a4.z, vv, acc[4 * u + 2]);
                acc[4 * u + 3] = fmaf(a4.w, vv, acc[4 * u + 3]);
            }
        }
    }
#pragma unroll
    for (int j = 0; j < 32; ++j) {
        int c = cg * 32 + j;
        g_xc[b][c][n] = acc[j] + q[((size_t)b * C_ + c) * P_ + n];
    }
}

// =============================================================================
// 6) conv5x5 on tensor cores: 25 tap-GEMMs, bf16 3-term split, fused LN
//    partials. grid (pt=8, b=8, st=2) = 128 blocks, 256 threads (8 warps).
//    smem: image h [0,36864), image e [36864,73728), W double buf [73728,106496)
// =============================================================================
#define CV_IMG_H 0
#define CV_IMG_E 36864
#define CV_W     73728
#define CV_SMEM  106496

__global__ __launch_bounds__(256, 1)
void conv1_mma_kernel(const float* __restrict__ s_b1,
                      const float* __restrict__ c_b1)
{
    extern __shared__ char smem[];
    const uint32_t sb = smem_u32(smem);
    const int pt = blockIdx.x;
    const int b  = blockIdx.y;
    const int st = blockIdx.z;
    const int tid = threadIdx.x;
    const int wid = tid >> 5;
    const int lane = tid & 31;
    const float* x    = st ? &g_xc[b][0][0] : &g_xs[b][0][0];
    const float* bias = st ? c_b1 : s_b1;

    const int l7   = lane & 7;
    const int a_co = lane >> 4;
    const int hi16 = lane >> 4;
    const int c8   = (lane >> 3) & 1;

    // this lane's pixel for A fragments (m16 per warp)
    const int apx = wid * 16 + l7 + c8 * 8;        // 0..127
    const int padbase = (apx >> 5) * 36 + (apx & 31);

    // ---- stage padded image (8 rows x 36 cols x 64 ci) as bf16 h/e ----
    for (int i = tid; i < 18432; i += 256) {
        int cc = i % 36;
        int rest = i / 36;
        int ci = rest & 63, rl = rest >> 6;
        int r = 4 * pt + rl - 2, c = cc - 2;
        float v = (r >= 0 && r < 32 && c >= 0 && c < 32)
                      ? x[ci * P_ + r * 32 + c] : 0.f;
        __nv_bfloat16 h = __float2bfloat16(v);
        uint32_t byo = swz(rl * 36 + cc, ci >> 3) + (ci & 7) * 2;
        *(__nv_bfloat16*)(smem + CV_IMG_H + byo) = h;
        *(__nv_bfloat16*)(smem + CV_IMG_E + byo) =
            __float2bfloat16(v - __bfloat162float(h));
    }

    // ---- prefetch weights tap 0 ----
    {
        const size_t gbase = (size_t)(st * 25 + 0) * 4096;
        for (int i = tid; i < 1024; i += 256) {
            int half = i >> 9;
            int j = i & 511;
            int co = j >> 3, cx = j & 7;
            const __nv_bfloat16* gp = half ? g_W1e : g_W1h;
            cp16(sb + CV_W + half * 8192 + swz(co, cx),
                 gp + gbase + (size_t)co * 64 + cx * 8);
        }
        CP_COMMIT();
    }

    // ---- bias init ----
    float od[8][4];
#pragma unroll
    for (int jt = 0; jt < 8; jt++) {
        int co = 8 * jt + (lane & 3) * 2;
        float b0 = bias[co], b1 = bias[co + 1];
        od[jt][0] = b0; od[jt][1] = b1; od[jt][2] = b0; od[jt][3] = b1;
    }

    CP_WAIT0();
    __syncthreads();

    for (int tap = 0; tap < 25; ++tap) {
        const uint32_t wb = sb + CV_W + (tap & 1) * 16384;

        if (tap < 24) {
            const uint32_t ob = sb + CV_W + ((tap + 1) & 1) * 16384;
            const size_t gbase = (size_t)(st * 25 + tap + 1) * 4096;
            for (int i = tid; i < 1024; i += 256) {
                int half = i >> 9;
                int j = i & 511;
                int co = j >> 3, cx = j & 7;
                const __nv_bfloat16* gp = half ? g_W1e : g_W1h;
                cp16(ob + half * 8192 + swz(co, cx),
                     gp + gbase + (size_t)co * 64 + cx * 8);
            }
            CP_COMMIT();
        }

        const int dy = tap / 5, dx = tap - 5 * dy;
        const int pad = padbase + dy * 36 + dx;

        uint32_t Ah[4][4], Ae[4][4];
#pragma unroll
        for (int t4 = 0; t4 < 4; t4++) {
            ldsm4(Ah[t4], sb + CV_IMG_H + swz(pad, 2 * t4 + a_co));
            ldsm4(Ae[t4], sb + CV_IMG_E + swz(pad, 2 * t4 + a_co));
        }

#pragma unroll
        for (int t4 = 0; t4 < 4; t4++) {
#pragma unroll
            for (int jp = 0; jp < 4; jp++) {
                uint32_t krow = 8 * (2 * jp + hi16) + l7;
                uint32_t bh[4], be[4];
                ldsm4(bh, wb + swz(krow, 2 * t4 + c8));
                ldsm4(be, wb + 8192 + swz(krow, 2 * t4 + c8));
                mma16816(od[2 * jp],     Ah[t4], bh[0], bh[1]);
                mma16816(od[2 * jp + 1], Ah[t4], bh[2], bh[3]);
                mma16816(od[2 * jp],     Ae[t4], bh[0], bh[1]);
                mma16816(od[2 * jp + 1], Ae[t4], bh[2], bh[3]);
                mma16816(od[2 * jp],     Ah[t4], be[0], be[1]);
                mma16816(od[2 * jp + 1], Ah[t4], be[2], be[3]);
            }
        }

        if (tap < 24) {
            CP_WAIT0();
            __syncthreads();
        }
    }

    // ---- epilogue: write y1 + LN partial sums ----
    const int pxr_lo = wid * 16 + (lane >> 2);
    const int pxr_hi = pxr_lo + 8;
    float s = 0.f, s2 = 0.f;
#pragma unroll
    for (int j2 = 0; j2 < 8; j2++) {
        int co = 8 * j2 + (lane & 3) * 2;
        g_y1[st][b][co][pt * 128 + pxr_lo]     = od[j2][0];
        g_y1[st][b][co + 1][pt * 128 + pxr_lo] = od[j2][1];
        g_y1[st][b][co][pt * 128 + pxr_hi]     = od[j2][2];
        g_y1[st][b][co + 1][pt * 128 + pxr_hi] = od[j2][3];
#pragma unroll
        for (int xx = 0; xx < 4; xx++) {
            s += od[j2][xx];
            s2 = fmaf(od[j2][xx], od[j2][xx], s2);
        }
    }
#pragma unroll
    for (int off = 16; off > 0; off >>= 1) {
        s  += __shfl_xor_sync(0xffffffffu, s,  off);
        s2 += __shfl_xor_sync(0xffffffffu, s2, off);
    }
    __shared__ float rs[8], rs2[8];
    if (lane == 0) { rs[wid] = s; rs2[wid] = s2; }
    __syncthreads();
    if (tid == 0) {
        float S = 0.f, S2 = 0.f;
#pragma unroll
        for (int wv = 0; wv < 8; wv++) { S += rs[wv]; S2 += rs2[wv]; }
        g_part[st][b][pt][0] = S;
        g_part[st][b][pt][1] = S2;
    }
}

// =============================================================================
// 7) LN finalize. grid 16, 32 threads.
// =============================================================================
__global__ void ln_finalize_kernel()
{
    const int st = blockIdx.x >> 3, b = blockIdx.x & 7;
    if (threadIdx.x == 0) {
        float S = 0.f, S2 = 0.f;
#pragma unroll
        for (int g = 0; g < 8; g++) { S += g_part[st][b][g][0]; S2 += g_part[st][b][g][1]; }
        float inv = 1.f / (float)(C_ * P_);
        float mean = S * inv;
        float var  = S2 * inv - mean * mean;
        g_stats[st][b][0] = mean;
        g_stats[st][b][1] = rsqrtf(var + 1e-5f);
    }
}

// =============================================================================
// 8) LN apply + ReLU + 1x1 conv. grid (8,8,2), 128 threads.
// =============================================================================
__global__ __launch_bounds__(128, 1)
void conv2_kernel(const float* __restrict__ s_lnw, const float* __restrict__ s_lnb,
                  const float* __restrict__ s_w2,  const float* __restrict__ s_b2,
                  const float* __restrict__ c_lnw, const float* __restrict__ c_lnb,
                  const float* __restrict__ c_w2,  const float* __restrict__ c_b2,
                  float* __restrict__ out)
{
    __shared__ float Ws[64 * 128];
    const int pt = blockIdx.x;
    const int b  = blockIdx.y;
    const int st = blockIdx.z;
    const int tid = threadIdx.x;
    const float* lnw = st ? c_lnw : s_lnw;
    const float* lnb = st ? c_lnb : s_lnb;
    const float* w2  = st ? c_w2  : s_w2;
    const float* b2  = st ? c_b2  : s_b2;

    for (int i = tid; i < NH_ * C_; i += 128) {
        int nh = i >> 6, c = i & 63;
        Ws[c * NH_ + nh] = w2[i];
    }
    __syncthreads();

    const int p = pt * 128 + tid;
    const float mean = g_stats[st][b][0];
    const float rstd = g_stats[st][b][1];

    float acc[NH_];
#pragma unroll
    for (int nh = 0; nh < NH_; nh++) acc[nh] = 0.f;

    for (int c = 0; c < 64; ++c) {
        float yv = g_y1[st][b][c][p];
        float t = (yv - mean) * rstd;
        t = fmaf(t, lnw[c * P_ + p], lnb[c * P_ + p]);
        t = fmaxf(t, 0.f);
#pragma unroll
        for (int u = 0; u < 32; ++u) {
            float4 w4 = *(const float4*)&Ws[c * NH_ + 4 * u];
            acc[4 * u + 0] = fmaf(w4.x, t, acc[4 * u + 0]);
            acc[4 * u + 1] = fmaf(w4.y, t, acc[4 * u + 1]);
            acc[4 * u + 2] = fmaf(w4.z, t, acc[4 * u + 2]);
            acc[4 * u + 3] = fmaf(w4.w, t, acc[4 * u + 3]);
        }
    }
    float* ob = out + ((size_t)st * B_ + b) * NH_ * P_;
#pragma unroll
    for (int nh = 0; nh < NH_; nh++)
        ob[(size_t)nh * P_ + p] = acc[nh] + b2[nh];
}

// =============================================================================
// host launcher — flash at launch index 3 (ncu capture slot).
// =============================================================================
extern "C" void kernel_launch(void* const* d_in, const int* in_sizes, int n_in,
                              void* d_out, int out_size)
{
    const float* q    = (const float*)d_in[0];
    const float* keys = (const float*)d_in[1];
    const float* vals = (const float*)d_in[2];
    const float* s_w1 = (const float*)d_in[3];
    const float* s_b1 = (const float*)d_in[4];
    const float* s_lnw = (const float*)d_in[5];
    const float* s_lnb = (const float*)d_in[6];
    const float* s_w2 = (const float*)d_in[7];
    const float* s_b2 = (const float*)d_in[8];
    const float* c_w1 = (const float*)d_in[9];
    const float* c_b1 = (const float*)d_in[10];
    const float* c_lnw = (const float*)d_in[11];
    const float* c_lnb = (const float*)d_in[12];
    const float* c_w2 = (const float*)d_in[13];
    const float* c_b2 = (const float*)d_in[14];
    float* out = (float*)d_out;

    cudaFuncSetAttribute(flash_mma_kernel,
                         cudaFuncAttributeMaxDynamicSharedMemorySize, FL_SMEM);
    cudaFuncSetAttribute(ca_logits_kernel,
                         cudaFuncAttributeMaxDynamicSharedMemorySize, CL_SMEM);
    cudaFuncSetAttribute(conv1_mma_kernel,
                         cudaFuncAttributeMaxDynamicSharedMemorySize, CV_SMEM);

    convert_w1_kernel<<<dim3(25, 2), 256>>>(s_w1, c_w1);          // idx 0
    convert_kv_kernel<<<dim3(64, 2), 256>>>(keys, vals);          // idx 1
    ca_logits_kernel<<<dim3(8, 2, 8), 256, CL_SMEM>>>(q, keys);   // idx 2
    flash_mma_kernel<<<dim3(4, 16, 8), 128, FL_SMEM>>>(q);        // idx 3 (ncu)
    ca_softmax_kernel<<<dim3(64, 8), 128>>>();                    // idx 4
    combine_kernel<<<dim3(8, 8), 256>>>(q);                       // idx 5
    ca_apply_kernel<<<dim3(16, 8), 128>>>(q, vals);               // idx 6
    conv1_mma_kernel<<<dim3(8, 8, 2), 256, CV_SMEM>>>(s_b1, c_b1);// idx 7
    ln_finalize_kernel<<<16, 32>>>();                             // idx 8
    conv2_kernel<<<dim3(8, 8, 2), 128>>>(s_lnw, s_lnb, s_w2, s_b2,
                                         c_lnw, c_lnb, c_w2, c_b2, out);
}

// round 17
// speedup vs baseline: 1.1828x; 1.1828x over previous
#include <cuda_runtime.h>
#include <cuda_bf16.h>
#include <math.h>
#include <stdint.h>

#define B_  8
#define L_  8
#define C_  64
#define P_  1024
#define NH_ 128
#define MCH 512
#define LOG2E 1.4426950408889634f

// ---------------- scratch (static device memory) -----------------------------
__device__ float g_Opart[4][B_][P_][C_];
__device__ float g_m[4][B_][P_];
__device__ float g_l[4][B_][P_];
__device__ float g_xs[B_][C_][P_];
__device__ float g_xc[B_][C_][P_];
__device__ float g_att[B_][C_][MCH];
__device__ float g_attp[2][B_][C_][MCH];
__device__ float g_y1[2][B_][C_][P_];
__device__ float g_part[2][B_][8][2];
__device__ __align__(16) __nv_bfloat16 g_Kh[B_ * L_ * P_ * C_];
__device__ __align__(16) __nv_bfloat16 g_Ke[B_ * L_ * P_ * C_];
__device__ __align__(16) __nv_bfloat16 g_Vh[B_ * L_ * P_ * C_];
__device__ __align__(16) __nv_bfloat16 g_Ve[B_ * L_ * P_ * C_];

// ---------------- helpers -----------------------------------------------------
__device__ __forceinline__ uint32_t smem_u32(const void* p) {
    uint32_t a;
    asm("{ .reg .u64 t; cvta.to.shared.u64 t, %1; cvt.u32.u64 %0, t; }"
        : "=r"(a) : "l"(p));
    return a;
}
__device__ __forceinline__ void ldsm4(uint32_t* r, uint32_t addr) {
    asm volatile("ldmatrix.sync.aligned.m8n8.x4.shared.b16 {%0,%1,%2,%3}, [%4];"
        : "=r"(r[0]), "=r"(r[1]), "=r"(r[2]), "=r"(r[3]) : "r"(addr));
}
__device__ __forceinline__ void ldsm4t(uint32_t* r, uint32_t addr) {
    asm volatile("ldmatrix.sync.aligned.m8n8.x4.trans.shared.b16 {%0,%1,%2,%3}, [%4];"
        : "=r"(r[0]), "=r"(r[1]), "=r"(r[2]), "=r"(r[3]) : "r"(addr));
}
__device__ __forceinline__ void mma16816(float* d, const uint32_t* a,
                                         uint32_t b0, uint32_t b1) {
    asm volatile("mma.sync.aligned.m16n8k16.row.col.f32.bf16.bf16.f32 "
        "{%0,%1,%2,%3}, {%4,%5,%6,%7}, {%8,%9}, {%0,%1,%2,%3};"
        : "+f"(d[0]), "+f"(d[1]), "+f"(d[2]), "+f"(d[3])
        : "r"(a[0]), "r"(a[1]), "r"(a[2]), "r"(a[3]), "r"(b0), "r"(b1));
}
__device__ __forceinline__ uint32_t bf2pack(float lo, float hi) {
    uint32_t r;
    asm("cvt.rn.bf16x2.f32 %0, %1, %2;" : "=r"(r) : "f"(hi), "f"(lo));
    return r;
}
__device__ __forceinline__ void cp16(uint32_t saddr, const void* g) {
    asm volatile("cp.async.cg.shared.global [%0], [%1], 16;"
                 :: "r"(saddr), "l"(g) : "memory");
}
#define CP_COMMIT() asm volatile("cp.async.commit_group;" ::: "memory")
#define CP_WAIT0()  asm volatile("cp.async.wait_group 0;" ::: "memory")
__device__ __forceinline__ uint32_t swz(int row, int chunk) {
    return (uint32_t)(row * 128 + ((chunk ^ (row & 7)) << 4));
}

// =============================================================================
// 0) Pre-pass: fp32 [b][l][c][p] -> bf16 h/e in [b][l][p][c]. grid (64, 2).
// =============================================================================
__global__ __launch_bounds__(256, 1)
void convert_kv_kernel(const float* __restrict__ keys,
                       const float* __restrict__ vals)
{
    __shared__ __nv_bfloat16 shH[64][68], shE[64][68];
    const int bl = blockIdx.x;
    const int kv = blockIdx.y;
    const int tid = threadIdx.x;
    const float* src = (kv ? vals : keys) + (size_t)bl * 65536;
    __nv_bfloat16* dh = (kv ? g_Vh : g_Kh) + (size_t)bl * 65536;
    __nv_bfloat16* de = (kv ? g_Ve : g_Ke) + (size_t)bl * 65536;

    for (int it = 0; it < 16; ++it) {
        const int p0 = it * 64;
        __syncthreads();
        for (int i4 = tid; i4 < 1024; i4 += 256) {
            int c = i4 >> 4, p4 = (i4 & 15) << 2;
            float4 v = *(const float4*)(src + c * P_ + p0 + p4);
            float vv[4] = {v.x, v.y, v.z, v.w};
#pragma unroll
            for (int u = 0; u < 4; u++) {
                __nv_bfloat16 h = __float2bfloat16(vv[u]);
                shH[p4 + u][c] = h;
                shE[p4 + u][c] = __float2bfloat16(vv[u] - __bfloat162float(h));
            }
        }
        __syncthreads();
        for (int i4 = tid; i4 < 1024; i4 += 256) {
            int p = i4 >> 4, c4 = (i4 & 15) << 2;
            size_t o = (size_t)(p0 + p) * 64 + c4;
            *(uint2*)(dh + o) = *(const uint2*)&shH[p][c4];
            *(uint2*)(de + o) = *(const uint2*)&shE[p][c4];
        }
    }
}

// =============================================================================
// 1) Flash spatial attention. 128 threads, TQ=64, ks=4. grid (4,16,8).
//    Q pre-scaled by log2(e); softmax in exp2 domain.
// =============================================================================
#define KVB 32768
#define FL_SMEM 65536

__global__ __launch_bounds__(128, 3)
void flash_mma_kernel(const float* __restrict__ q)
{
    extern __shared__ char smem[];
    const uint32_t sb = smem_u32(smem);
    const int ks = blockIdx.x;
    const int qt = blockIdx.y;
    const int b  = blockIdx.z;
    const int tid = threadIdx.x;
    const int wid = tid >> 5;
    const int lane = tid & 31;

    const int l7 = lane & 7;
    const int a_row = wid * 16 + l7 + ((lane >> 3) & 1) * 8;
    const int a_co  = lane >> 4;
    const int hi16  = lane >> 4;
    const int c8    = (lane >> 3) & 1;
    const int grp   = lane >> 2;
    const int qr_lo = wid * 16 + grp;
    const int qr_hi = qr_lo + 8;

    const int kbase = b * 8192 + ks * 2048;

    const float* qg = q + (size_t)b * C_ * P_ + qt * 64;
    for (int i = tid; i < 4096; i += 128) {
        int c = i >> 6, qq = i & 63;
        float v = qg[c * P_ + qq] * LOG2E;
        __nv_bfloat16 h = __float2bfloat16(v);
        uint32_t byo = swz(qq, c >> 3) + (c & 7) * 2;
        *(__nv_bfloat16*)(smem + byo) = h;
        *(__nv_bfloat16*)(smem + 8192 + byo) =
            __float2bfloat16(v - __bfloat162float(h));
    }
    __syncthreads();

    uint32_t qhf[4][4], qef[4][4];
#pragma unroll
    for (int t4 = 0; t4 < 4; t4++) {
        ldsm4(qhf[t4], sb + swz(a_row, 2 * t4 + a_co));
        ldsm4(qef[t4], sb + 8192 + swz(a_row, 2 * t4 + a_co));
    }
    __syncthreads();

    {
        const size_t gb = (size_t)kbase * 64;
#pragma unroll
        for (int kk = 0; kk < 16; kk++) {
            int i = tid + 128 * kk;
            int buf = i >> 9;
            int j = i & 511;
            int r = j >> 3, cx = j & 7;
            const __nv_bfloat16* gp =
                (buf == 0) ? g_Kh : (buf == 1) ? g_Ke : (buf == 2) ? g_Vh : g_Ve;
            cp16(sb + buf * 8192 + swz(r, cx), gp + gb + (size_t)r * 64 + cx * 8);
        }
        CP_COMMIT();
    }

    float sd[8][4];
    float od[8][4];
    float m_lo = -1e30f, m_hi = -1e30f, l_lo = 0.f, l_hi = 0.f;
#pragma unroll
    for (int j = 0; j < 8; j++)
#pragma unroll
        for (int x = 0; x < 4; x++) od[j][x] = 0.f;

    for (int t = 0; t < 32; ++t) {
        CP_WAIT0();
        __syncthreads();
        const uint32_t bufb = sb + (t & 1) * KVB;

        if (t < 31) {
            const uint32_t ob = sb + ((t + 1) & 1) * KVB;
            const size_t gb = (size_t)(kbase + (t + 1) * 64) * 64;
#pragma unroll
            for (int kk = 0; kk < 16; kk++) {
                int i = tid + 128 * kk;
                int buf = i >> 9;
                int j = i & 511;
                int r = j >> 3, cx = j & 7;
                const __nv_bfloat16* gp =
                    (buf == 0) ? g_Kh : (buf == 1) ? g_Ke : (buf == 2) ? g_Vh : g_Ve;
                cp16(ob + buf * 8192 + swz(r, cx), gp + gb + (size_t)r * 64 + cx * 8);
            }
            CP_COMMIT();
        }

        const uint32_t SKH = bufb, SKE = bufb + 8192;
        const uint32_t SVH = bufb + 16384, SVE = bufb + 24576;

#pragma unroll
        for (int j = 0; j < 8; j++)
#pragma unroll
            for (int x = 0; x < 4; x++) sd[j][x] = 0.f;

#pragma unroll
        for (int t4 = 0; t4 < 4; t4++) {
#pragma unroll
            for (int jp = 0; jp < 4; jp++) {
                uint32_t kaddr_row = 8 * (2 * jp + hi16) + l7;
                uint32_t kh4[4], ke4[4];
                ldsm4(kh4, SKH + swz(kaddr_row, 2 * t4 + c8));
                ldsm4(ke4, SKE + swz(kaddr_row, 2 * t4 + c8));
                mma16816(sd[2 * jp],     qhf[t4], kh4[0], kh4[1]);
                mma16816(sd[2 * jp + 1], qhf[t4], kh4[2], kh4[3]);
                mma16816(sd[2 * jp],     qhf[t4], ke4[0], ke4[1]);
                mma16816(sd[2 * jp + 1], qhf[t4], ke4[2], ke4[3]);
                mma16816(sd[2 * jp],     qef[t4], kh4[0], kh4[1]);
                mma16816(sd[2 * jp + 1], qef[t4], kh4[2], kh4[3]);
            }
        }

        float mx_lo = sd[0][0], mx_hi = sd[0][2];
#pragma unroll
        for (int j = 0; j < 8; j++) {
            mx_lo = fmaxf(mx_lo, fmaxf(sd[j][0], sd[j][1]));
            mx_hi = fmaxf(mx_hi, fmaxf(sd[j][2], sd[j][3]));
        }
        mx_lo = fmaxf(mx_lo, __shfl_xor_sync(0xffffffffu, mx_lo, 1));
        mx_lo = fmaxf(mx_lo, __shfl_xor_sync(0xffffffffu, mx_lo, 2));
        mx_hi = fmaxf(mx_hi, __shfl_xor_sync(0xffffffffu, mx_hi, 1));
        mx_hi = fmaxf(mx_hi, __shfl_xor_sync(0xffffffffu, mx_hi, 2));
        float mn_lo = fmaxf(m_lo, mx_lo), mn_hi = fmaxf(m_hi, mx_hi);
        float al_lo = exp2f(m_lo - mn_lo), al_hi = exp2f(m_hi - mn_hi);
        m_lo = mn_lo; m_hi = mn_hi;

        float rs_lo = 0.f, rs_hi = 0.f;
#pragma unroll
        for (int j = 0; j < 8; j++) {
            sd[j][0] = exp2f(sd[j][0] - mn_lo);
            sd[j][1] = exp2f(sd[j][1] - mn_lo);
            sd[j][2] = exp2f(sd[j][2] - mn_hi);
            sd[j][3] = exp2f(sd[j][3] - mn_hi);
            rs_lo += sd[j][0] + sd[j][1];
            rs_hi += sd[j][2] + sd[j][3];
        }
        rs_lo += __shfl_xor_sync(0xffffffffu, rs_lo, 1);
        rs_lo += __shfl_xor_sync(0xffffffffu, rs_lo, 2);
        rs_hi += __shfl_xor_sync(0xffffffffu, rs_hi, 1);
        rs_hi += __shfl_xor_sync(0xffffffffu, rs_hi, 2);
        l_lo = l_lo * al_lo + rs_lo;
        l_hi = l_hi * al_hi + rs_hi;

#pragma unroll
        for (int j = 0; j < 8; j++) {
            od[j][0] *= al_lo; od[j][1] *= al_lo;
            od[j][2] *= al_hi; od[j][3] *= al_hi;
        }

        uint32_t pha[4][4], pea[4][4];
#pragma unroll
        for (int t4 = 0; t4 < 4; t4++) {
            int j0 = 2 * t4, j1 = 2 * t4 + 1;
            float e[8];
#pragma unroll
            for (int u = 0; u < 4; u++) {
                float p0f = sd[j0][u];
                float p1f = sd[j1][u];
                e[u]     = p0f - __bfloat162float(__float2bfloat16(p0f));
                e[4 + u] = p1f - __bfloat162float(__float2bfloat16(p1f));
            }
            pha[t4][0] = bf2pack(sd[j0][0], sd[j0][1]);
            pha[t4][1] = bf2pack(sd[j0][2], sd[j0][3]);
            pha[t4][2] = bf2pack(sd[j1][0], sd[j1][1]);
            pha[t4][3] = bf2pack(sd[j1][2], sd[j1][3]);
            pea[t4][0] = bf2pack(e[0], e[1]);
            pea[t4][1] = bf2pack(e[2], e[3]);
            pea[t4][2] = bf2pack(e[4], e[5]);
            pea[t4][3] = bf2pack(e[6], e[7]);
        }

#pragma unroll
        for (int t4 = 0; t4 < 4; t4++) {
            uint32_t vrow = 16 * t4 + l7 + 8 * c8;
#pragma unroll
            for (int jp = 0; jp < 4; jp++) {
                int j2 = 2 * jp;
                uint32_t vh4[4], ve4[4];
                ldsm4t(vh4, SVH + swz(vrow, j2 + hi16));
                ldsm4t(ve4, SVE + swz(vrow, j2 + hi16));
                mma16816(od[j2],     pha[t4], vh4[0], vh4[1]);
                mma16816(od[j2 + 1], pha[t4], vh4[2], vh4[3]);
                mma16816(od[j2],     pea[t4], vh4[0], vh4[1]);
                mma16816(od[j2 + 1], pea[t4], vh4[2], vh4[3]);
                mma16816(od[j2],     pha[t4], ve4[0], ve4[1]);
                mma16816(od[j2 + 1], pha[t4], ve4[2], ve4[3]);
            }
        }
    }

    if ((lane & 3) == 0) {
        g_m[ks][b][qt * 64 + qr_lo] = m_lo;
        g_l[ks][b][qt * 64 + qr_lo] = l_lo;
        g_m[ks][b][qt * 64 + qr_hi] = m_hi;
        g_l[ks][b][qt * 64 + qr_hi] = l_hi;
    }
#pragma unroll
    for (int j2 = 0; j2 < 8; j2++) {
        int c = 8 * j2 + (lane & 3) * 2;
        g_Opart[ks][b][qt * 64 + qr_lo][c]     = od[j2][0];
        g_Opart[ks][b][qt * 64 + qr_lo][c + 1] = od[j2][1];
        g_Opart[ks][b][qt * 64 + qr_hi][c]     = od[j2][2];
        g_Opart[ks][b][qt * 64 + qr_hi][c + 1] = od[j2][3];
    }
}

// =============================================================================
// 2) Merged: combine (blocks 0..7) + channel apply (blocks 8..23). grid (24,8),
//    256 threads. Both roles independent; combine m/l in exp2 domain.
// =============================================================================
__global__ __launch_bounds__(256, 1)
void combine_apply_kernel(const float* __restrict__ q,
                          const float* __restrict__ vals)
{
    const int role = blockIdx.x;
    const int b = blockIdx.y;
    const int tid = threadIdx.x;

    if (role < 8) {
        // ---- combine 4 key-splits + residual ----
        const int qt = role;
        for (int i = tid; i < 128 * 64; i += 256) {
            int qq = qt * 128 + (i >> 6);
            int c  = i & 63;
            float m0 = g_m[0][b][qq], m1 = g_m[1][b][qq];
            float m2 = g_m[2][b][qq], m3 = g_m[3][b][qq];
            float M  = fmaxf(fmaxf(m0, m1), fmaxf(m2, m3));
            float e0 = exp2f(m0 - M), e1 = exp2f(m1 - M);
            float e2 = exp2f(m2 - M), e3 = exp2f(m3 - M);
            float denom = g_l[0][b][qq] * e0 + g_l[1][b][qq] * e1 +
                          g_l[2][b][qq] * e2 + g_l[3][b][qq] * e3;
            float val = (g_Opart[0][b][qq][c] * e0 + g_Opart[1][b][qq][c] * e1 +
                         g_Opart[2][b][qq][c] * e2 + g_Opart[3][b][qq][c] * e3) / denom;
            g_xs[b][c][qq] = val + q[((size_t)b * C_ + c) * P_ + qq];
        }
    } else {
        // ---- channel apply + residual: nt in 0..15, 64 n per block ----
        __shared__ float As[128 * 68];
        const int nt = role - 8;
        const int n  = nt * 64 + (tid & 63);
        const int cg = tid >> 6;                 // 0..3, 16 channels each

        float acc[16];
#pragma unroll
        for (int j = 0; j < 16; j++) acc[j] = 0.f;

        const float* vb = vals + (size_t)b * MCH * P_;

        for (int mc = 0; mc < 4; ++mc) {
            __syncthreads();
            for (int i = tid; i < 8192; i += 256) {
                int c = i >> 7, mm = i & 127;
                As[mm * 68 + c] = g_att[b][c][mc * 128 + mm];
            }
            __syncthreads();
#pragma unroll 2
            for (int mm = 0; mm < 128; ++mm) {
                float vv = vb[(size_t)(mc * 128 + mm) * P_ + n];
#pragma unroll
                for (int u = 0; u < 4; ++u) {
                    float4 a4 = *(const float4*)&As[mm * 68 + cg * 16 + 4 * u];
                    acc[4 * u + 0] = fmaf(a4.x, vv, acc[4 * u + 0]);
                    acc[4 * u + 1] = fmaf(a4.y, vv, acc[4 * u + 1]);
                    acc[4 * u + 2] = fmaf(a4.z, vv, acc[4 * u + 2]);
                    acc[4 * u + 3] = fmaf(a4.w, vv, acc[4 * u + 3]);
                }
            }
        }
#pragma unroll
        for (int j = 0; j < 16; ++j) {
            int c = cg * 16 + j;
            g_xc[b][c][n] = acc[j] + q[((size_t)b * C_ + c) * P_ + n];
        }
    }
}

// =============================================================================
// 3) Channel logit partials. grid (mt=8, nh=2, b=8), 256 threads.
// =============================================================================
#define CLS 132
#define CL_SMEM (2 * 64 * CLS * 4)

__global__ __launch_bounds__(256, 1)
void ca_logits_kernel(const float* __restrict__ q,
                      const float* __restrict__ keys)
{
    extern __shared__ float sm[];
    float* Qs = sm;
    float* Ks = sm + 64 * CLS;
    const int mt = blockIdx.x;
    const int nh = blockIdx.y;
    const int b  = blockIdx.z;
    const int tid = threadIdx.x;
    const int ty = tid >> 4, tx = tid & 15;

    float acc[4][4];
#pragma unroll
    for (int i = 0; i < 4; i++)
#pragma unroll
        for (int j = 0; j < 4; j++) acc[i][j] = 0.f;

    const float* qb = q + (size_t)b * C_ * P_ + nh * 512;
    const float* kb = keys + (size_t)b * MCH * P_ + nh * 512;

    for (int nt = 0; nt < 4; ++nt) {
        __syncthreads();
        for (int i4 = tid; i4 < 2048; i4 += 256) {
            int r = i4 >> 5, n4 = (i4 & 31) << 2;
            *(float4*)&Qs[r * CLS + n4] = *(const float4*)(qb + r * P_ + nt * 128 + n4);
            *(float4*)&Ks[r * CLS + n4] =
                *(const float4*)(kb + (size_t)(mt * 64 + r) * P_ + nt * 128 + n4);
        }
        __syncthreads();
#pragma unroll 4
        for (int n = 0; n < 128; ++n) {
            float qv[4], kv[4];
#pragma unroll
            for (int i = 0; i < 4; i++) qv[i] = Qs[(ty + 16 * i) * CLS + n];
#pragma unroll
            for (int j = 0; j < 4; j++) kv[j] = Ks[(tx + 16 * j) * CLS + n];
#pragma unroll
            for (int i = 0; i < 4; i++)
#pragma unroll
                for (int j = 0; j < 4; j++)
                    acc[i][j] = fmaf(qv[i], kv[j], acc[i][j]);
        }
    }
#pragma unroll
    for (int i = 0; i < 4; i++)
#pragma unroll
        for (int j = 0; j < 4; j++)
            g_attp[nh][b][ty + 16 * i][mt * 64 + tx + 16 * j] = acc[i][j];
}

// =============================================================================
// 4) Row softmax (sums partials). grid (64, 8), 128 threads.
// =============================================================================
__global__ void ca_softmax_kernel()
{
    const int c = blockIdx.x;
    const int b = blockIdx.y;
    const int tid = threadIdx.x;
    float v[4];
#pragma unroll
    for (int r = 0; r < 4; r++)
        v[r] = g_attp[0][b][c][tid + 128 * r] + g_attp[1][b][c][tid + 128 * r];
    float mx = fmaxf(fmaxf(v[0], v[1]), fmaxf(v[2], v[3]));
#pragma unroll
    for (int off = 16; off > 0; off >>= 1)
        mx = fmaxf(mx, __shfl_xor_sync(0xffffffffu, mx, off));
    __shared__ float red[4], red2[4];
    if ((tid & 31) == 0) red[tid >> 5] = mx;
    __syncthreads();
    mx = fmaxf(fmaxf(red[0], red[1]), fmaxf(red[2], red[3]));
    float s = 0.f;
#pragma unroll
    for (int r = 0; r < 4; r++) { v[r] = __expf(v[r] - mx); s += v[r]; }
#pragma unroll
    for (int off = 16; off > 0; off >>= 1)
        s += __shfl_xor_sync(0xffffffffu, s, off);
    if ((tid & 31) == 0) red2[tid >> 5] = s;
    __syncthreads();
    s = red2[0] + red2[1] + red2[2] + red2[3];
    float inv = 1.f / s;
#pragma unroll
    for (int r = 0; r < 4; r++) g_att[b][c][tid + 128 * r] = v[r] * inv;
}

// =============================================================================
// 5) conv5x5 (8 out-ch/block) + fused LN partial sums. grid (8,8,2), 256 thr,
//    2 CTAs/SM.
// =============================================================================
#define C1_WOF 0
#define C1_XOF 12800
#define C1_SMEM ((12800 + 1296) * 4)

__global__ __launch_bounds__(256, 2)
void conv1_kernel(const float* __restrict__ s_w1, const float* __restrict__ s_b1,
                  const float* __restrict__ c_w1, const float* __restrict__ c_b1)
{
    extern __shared__ float sm[];
    const int cog = blockIdx.x;
    const int b   = blockIdx.y;
    const int st  = blockIdx.z;
    const int tid = threadIdx.x;
    const float* w    = st ? c_w1 : s_w1;
    const float* bias = st ? c_b1 : s_b1;
    const float* x    = st ? &g_xc[b][0][0] : &g_xs[b][0][0];
    const int co0 = cog * 8;

    for (int i = tid; i < 12800; i += 256) {
        int u = i / 1600, r = i - u * 1600;
        sm[C1_WOF + r * 8 + u] = w[(size_t)(co0 + u) * 1600 + r];
    }

    float acc[8][4];
#pragma unroll
    for (int u = 0; u < 8; u++) {
        float bv = bias[co0 + u];
#pragma unroll
        for (int r = 0; r < 4; r++) acc[u][r] = bv;
    }

    int pi[4], pj[4];
#pragma unroll
    for (int r = 0; r < 4; r++) {
        int p = tid + 256 * r;
        pi[r] = p >> 5;
        pj[r] = p & 31;
    }

    for (int ci = 0; ci < 64; ++ci) {
        __syncthreads();
        for (int i = tid; i < 1296; i += 256) {
            int rr = i / 36 - 2, cc = i % 36 - 2;
            sm[C1_XOF + i] = (rr >= 0 && rr < 32 && cc >= 0 && cc < 32)
                                 ? x[ci * P_ + rr * 32 + cc] : 0.f;
        }
        __syncthreads();
#pragma unroll
        for (int dy = 0; dy < 5; ++dy) {
#pragma unroll
            for (int dx = 0; dx < 5; ++dx) {
                float xv[4];
#pragma unroll
                for (int r = 0; r < 4; r++)
                    xv[r] = sm[C1_XOF + (pi[r] + dy) * 36 + pj[r] + dx];
                const float* wt = &sm[C1_WOF + (ci * 25 + dy * 5 + dx) * 8];
                float4 w0 = *(const float4*)wt;
                float4 w1 = *(const float4*)(wt + 4);
                float wv[8] = {w0.x, w0.y, w0.z, w0.w, w1.x, w1.y, w1.z, w1.w};
#pragma unroll
                for (int u = 0; u < 8; ++u)
#pragma unroll
                    for (int r = 0; r < 4; r++)
                        acc[u][r] = fmaf(wv[u], xv[r], acc[u][r]);
            }
        }
    }

    float s = 0.f, s2 = 0.f;
#pragma unroll
    for (int u = 0; u < 8; ++u)
#pragma unroll
        for (int r = 0; r < 4; ++r) {
            float v = acc[u][r];
            g_y1[st][b][co0 + u][tid + 256 * r] = v;
            s += v;
            s2 = fmaf(v, v, s2);
        }

#pragma unroll
    for (int off = 16; off > 0; off >>= 1) {
        s  += __shfl_xor_sync(0xffffffffu, s,  off);
        s2 += __shfl_xor_sync(0xffffffffu, s2, off);
    }
    __shared__ float rs[8], rs2[8];
    if ((tid & 31) == 0) { rs[tid >> 5] = s; rs2[tid >> 5] = s2; }
    __syncthreads();
    if (tid == 0) {
        float S = 0.f, S2 = 0.f;
#pragma unroll
        for (int wv = 0; wv < 8; wv++) { S += rs[wv]; S2 += rs2[wv]; }
        g_part[st][b][cog][0] = S;
        g_part[st][b][cog][1] = S2;
    }
}

// =============================================================================
// 6) LN finalize (inline) + LN apply + ReLU + 1x1 conv. grid (8,8,2), 128 thr.
// =============================================================================
__global__ __launch_bounds__(128, 1)
void conv2_kernel(const float* __restrict__ s_lnw, const float* __restrict__ s_lnb,
                  const float* __restrict__ s_w2,  const float* __restrict__ s_b2,
                  const float* __restrict__ c_lnw, const float* __restrict__ c_lnb,
                  const float* __restrict__ c_w2,  const float* __restrict__ c_b2,
                  float* __restrict__ out)
{
    __shared__ float Ws[64 * 128];
    const int pt = blockIdx.x;
    const int b  = blockIdx.y;
    const int st = blockIdx.z;
    const int tid = threadIdx.x;
    const float* lnw = st ? c_lnw : s_lnw;
    const float* lnb = st ? c_lnb : s_lnb;
    const float* w2  = st ? c_w2  : s_w2;
    const float* b2  = st ? c_b2  : s_b2;

    for (int i = tid; i < NH_ * C_; i += 128) {
        int nh = i >> 6, c = i & 63;
        Ws[c * NH_ + nh] = w2[i];
    }
    __syncthreads();

    // inline LN stats from conv1 partials (16 floats; every thread redundantly)
    float S = 0.f, S2 = 0.f;
#pragma unroll
    for (int g = 0; g < 8; g++) { S += g_part[st][b][g][0]; S2 += g_part[st][b][g][1]; }
    const float invn = 1.f / (float)(C_ * P_);
    const float mean = S * invn;
    const float rstd = rsqrtf(S2 * invn - mean * mean + 1e-5f);

    const int p = pt * 128 + tid;

    float acc[NH_];
#pragma unroll
    for (int nh = 0; nh < NH_; nh++) acc[nh] = 0.f;

    for (int c = 0; c < 64; ++c) {
        float yv = g_y1[st][b][c][p];
        float t = (yv - mean) * rstd;
        t = fmaf(t, lnw[c * P_ + p], lnb[c * P_ + p]);
        t = fmaxf(t, 0.f);
#pragma unroll
        for (int u = 0; u < 32; ++u) {
            float4 w4 = *(const float4*)&Ws[c * NH_ + 4 * u];
            acc[4 * u + 0] = fmaf(w4.x, t, acc[4 * u + 0]);
            acc[4 * u + 1] = fmaf(w4.y, t, acc[4 * u + 1]);
            acc[4 * u + 2] = fmaf(w4.z, t, acc[4 * u + 2]);
            acc[4 * u + 3] = fmaf(w4.w, t, acc[4 * u + 3]);
        }
    }
    float* ob = out + ((size_t)st * B_ + b) * NH_ * P_;
#pragma unroll
    for (int nh = 0; nh < NH_; nh++)
        ob[(size_t)nh * P_ + p] = acc[nh] + b2[nh];
}

// =============================================================================
// host launcher — flash at launch index 3 (ncu capture slot).
// =============================================================================
extern "C" void kernel_launch(void* const* d_in, const int* in_sizes, int n_in,
                              void* d_out, int out_size)
{
    const float* q    = (const float*)d_in[0];
    const float* keys = (const float*)d_in[1];
    const float* vals = (const float*)d_in[2];
    const float* s_w1 = (const float*)d_in[3];
    const float* s_b1 = (const float*)d_in[4];
    const float* s_lnw = (const float*)d_in[5];
    const float* s_lnb = (const float*)d_in[6];
    const float* s_w2 = (const float*)d_in[7];
    const float* s_b2 = (const float*)d_in[8];
    const float* c_w1 = (const float*)d_in[9];
    const float* c_b1 = (const float*)d_in[10];
    const float* c_lnw = (const float*)d_in[11];
    const float* c_lnb = (const float*)d_in[12];
    const float* c_w2 = (const float*)d_in[13];
    const float* c_b2 = (const float*)d_in[14];
    float* out = (float*)d_out;

    cudaFuncSetAttribute(flash_mma_kernel,
                         cudaFuncAttributeMaxDynamicSharedMemorySize, FL_SMEM);
    cudaFuncSetAttribute(ca_logits_kernel,
                         cudaFuncAttributeMaxDynamicSharedMemorySize, CL_SMEM);
    cudaFuncSetAttribute(conv1_kernel,
                         cudaFuncAttributeMaxDynamicSharedMemorySize, C1_SMEM);

    convert_kv_kernel<<<dim3(64, 2), 256>>>(keys, vals);          // idx 0
    ca_logits_kernel<<<dim3(8, 2, 8), 256, CL_SMEM>>>(q, keys);   // idx 1
    ca_softmax_kernel<<<dim3(64, 8), 128>>>();                    // idx 2
    flash_mma_kernel<<<dim3(4, 16, 8), 128, FL_SMEM>>>(q);        // idx 3 (ncu)
    combine_apply_kernel<<<dim3(24, 8), 256>>>(q, vals);          // idx 4
    conv1_kernel<<<dim3(8, 8, 2), 256, C1_SMEM>>>(s_w1, s_b1, c_w1, c_b1);
    conv2_kernel<<<dim3(8, 8, 2), 128>>>(s_lnw, s_lnb, s_w2, s_b2,
                                         c_lnw, c_lnb, c_w2, c_b2, out);
}